// round 2
// baseline (speedup 1.0000x reference)
#include <cuda_runtime.h>
#include <math.h>

#define L 2048
#define H 512
#define NS 32
#define NLAY 4
#define CHUNK 128
#define NCH (L / CHUNK)   // 16

// ---------------- persistent scratch (no cudaMalloc allowed) ----------------
__device__ float  g_h[L * H];          // residual stream
__device__ float  g_u[L * H];          // layernorm output (scan input)
__device__ float  g_z[L * H];          // gelu(scan output)
__device__ float2 g_A[H * NS];         // Abar
__device__ float2 g_B[H * NS];         // Bbar
__device__ float2 g_Ap[H * NS];        // Abar^CHUNK
__device__ float2 g_sfin[NCH * H * NS];// per-chunk local final states
__device__ float2 g_sin [NCH * H * NS];// per-chunk initial states

// ---------------- encoder: h = x @ enc_w.T + enc_b ----------------
__global__ void enc_kernel(const float* __restrict__ x,
                           const float* __restrict__ w,
                           const float* __restrict__ b) {
    int idx = blockIdx.x * blockDim.x + threadIdx.x;   // L*H
    int l = idx >> 9, h = idx & 511;
    float4 xv = ((const float4*)x)[l];
    float4 wv = ((const float4*)w)[h];
    g_h[idx] = fmaf(xv.x, wv.x, fmaf(xv.y, wv.y, fmaf(xv.z, wv.z, fmaf(xv.w, wv.w, b[h]))));
}

// ---------------- layernorm: one block per row ----------------
__global__ void ln_kernel(const float* __restrict__ nw, const float* __restrict__ nb) {
    int l = blockIdx.x, t = threadIdx.x;               // 128 threads, float4 each
    float4 v = ((const float4*)(g_h + l * H))[t];
    float s = v.x + v.y + v.z + v.w;
    float q = v.x * v.x + v.y * v.y + v.z * v.z + v.w * v.w;
    for (int o = 16; o; o >>= 1) {
        s += __shfl_xor_sync(0xffffffffu, s, o);
        q += __shfl_xor_sync(0xffffffffu, q, o);
    }
    __shared__ float ss[4], sq[4];
    if ((t & 31) == 0) { ss[t >> 5] = s; sq[t >> 5] = q; }
    __syncthreads();
    s = ss[0] + ss[1] + ss[2] + ss[3];
    q = sq[0] + sq[1] + sq[2] + sq[3];
    float m = s * (1.0f / H);
    float var = q * (1.0f / H) - m * m;
    float r = rsqrtf(var + 1e-5f);
    float4 wv = ((const float4*)nw)[t], bv = ((const float4*)nb)[t];
    float4 o;
    o.x = fmaf((v.x - m) * r, wv.x, bv.x);
    o.y = fmaf((v.y - m) * r, wv.y, bv.y);
    o.z = fmaf((v.z - m) * r, wv.z, bv.z);
    o.w = fmaf((v.w - m) * r, wv.w, bv.w);
    ((float4*)(g_u + l * H))[t] = o;
}

// ---------------- per-layer discretization + A^CHUNK ----------------
__global__ void pre_kernel(const float* __restrict__ lre, const float* __restrict__ lim,
                           const float* __restrict__ bre, const float* __restrict__ bim,
                           const float* __restrict__ lstep) {
    int i = blockIdx.x * blockDim.x + threadIdx.x;     // H*NS
    int h = i >> 5;
    float st = expf(lstep[h]);
    float zr = 0.5f * st * lre[i], zi = 0.5f * st * lim[i];
    float dr = 1.0f - zr, di = -zi;                    // 1 - z
    float inv = 1.0f / (dr * dr + di * di);
    float blr = dr * inv, bli = -di * inv;             // BL = 1/(1-z)
    float nr = 1.0f + zr, ni = zi;                     // 1 + z
    float ar = blr * nr - bli * ni;
    float ai = blr * ni + bli * nr;
    float br_ = st * (blr * bre[i] - bli * bim[i]);
    float bi_ = st * (blr * bim[i] + bli * bre[i]);
    g_A[i] = make_float2(ar, ai);
    g_B[i] = make_float2(br_, bi_);
    float pr = ar, pi = ai;                            // A^128 via 7 squarings
    #pragma unroll
    for (int k = 0; k < 7; k++) { float tr = pr * pr - pi * pi; pi = 2.0f * pr * pi; pr = tr; }
    g_Ap[i] = make_float2(pr, pi);
}

// ---------------- scan pass 1: per-chunk local scan, zero init, states only --
// grid (NCH, H/32), block 128: 32 channels/block, 4 threads/channel, 8 states/thread
__global__ void scan1_kernel() {
    int chunk = blockIdx.x, hb = blockIdx.y * 32;
    int t = threadIdx.x, chl = t >> 2, part = t & 3;
    int h = hb + chl, n0 = part * 8;
    __shared__ float us[CHUNK * 32];
    for (int i = t; i < CHUNK * 32; i += 128)
        us[i] = g_u[(chunk * CHUNK + (i >> 5)) * H + hb + (i & 31)];
    __syncthreads();
    float ar[8], ai[8], br[8], bi[8], sr[8], si[8];
    #pragma unroll
    for (int k = 0; k < 8; k++) {
        float2 a = g_A[h * NS + n0 + k]; ar[k] = a.x; ai[k] = a.y;
        float2 b = g_B[h * NS + n0 + k]; br[k] = b.x; bi[k] = b.y;
        sr[k] = 0.0f; si[k] = 0.0f;
    }
    for (int j = 0; j < CHUNK; j++) {
        float u = us[j * 32 + chl];
        #pragma unroll
        for (int k = 0; k < 8; k++) {
            float nr = fmaf(ar[k], sr[k], fmaf(-ai[k], si[k], br[k] * u));
            float ni = fmaf(ar[k], si[k], fmaf( ai[k], sr[k], bi[k] * u));
            sr[k] = nr; si[k] = ni;
        }
    }
    #pragma unroll
    for (int k = 0; k < 8; k++)
        g_sfin[(chunk * H + h) * NS + n0 + k] = make_float2(sr[k], si[k]);
}

// ---------------- combine: propagate chunk-initial states ----------------
__global__ void comb_kernel() {
    int i = blockIdx.x * blockDim.x + threadIdx.x;     // H*NS
    float2 ap = g_Ap[i];
    float sr = 0.0f, si = 0.0f;
    #pragma unroll
    for (int c = 0; c < NCH; c++) {
        g_sin[c * H * NS + i] = make_float2(sr, si);
        float2 f = g_sfin[c * H * NS + i];
        float nr = ap.x * sr - ap.y * si + f.x;
        si      = ap.x * si + ap.y * sr + f.y;
        sr = nr;
    }
}

// ---------------- scan pass 3: full scan with correct init -> y -> gelu -----
__global__ void scan3_kernel(const float* __restrict__ cre, const float* __restrict__ cim,
                             const float* __restrict__ dvec) {
    int chunk = blockIdx.x, hb = blockIdx.y * 32;
    int t = threadIdx.x, chl = t >> 2, part = t & 3;
    int h = hb + chl, n0 = part * 8;
    __shared__ float us[CHUNK * 32];
    for (int i = t; i < CHUNK * 32; i += 128)
        us[i] = g_u[(chunk * CHUNK + (i >> 5)) * H + hb + (i & 31)];
    __syncthreads();
    float ar[8], ai[8], br[8], bi[8], cr[8], ci[8], sr[8], si[8];
    #pragma unroll
    for (int k = 0; k < 8; k++) {
        int idx = h * NS + n0 + k;
        float2 a = g_A[idx]; ar[k] = a.x; ai[k] = a.y;
        float2 b = g_B[idx]; br[k] = b.x; bi[k] = b.y;
        cr[k] = cre[idx];    ci[k] = cim[idx];
        float2 s0 = g_sin[chunk * H * NS + idx]; sr[k] = s0.x; si[k] = s0.y;
    }
    float dh = dvec[h];
    for (int j = 0; j < CHUNK; j++) {
        float u = us[j * 32 + chl];
        float acc = 0.0f;
        #pragma unroll
        for (int k = 0; k < 8; k++) {
            float nr = fmaf(ar[k], sr[k], fmaf(-ai[k], si[k], br[k] * u));
            float ni = fmaf(ar[k], si[k], fmaf( ai[k], sr[k], bi[k] * u));
            sr[k] = nr; si[k] = ni;
            acc = fmaf(cr[k], sr[k], acc);
            acc = fmaf(-ci[k], si[k], acc);
        }
        acc += __shfl_xor_sync(0xffffffffu, acc, 1);
        acc += __shfl_xor_sync(0xffffffffu, acc, 2);
        if (part == 0) {
            float y = fmaf(2.0f, acc, dh * u);
            float inner = 0.7978845608028654f * fmaf(0.044715f * y, y * y, y);
            float z = 0.5f * y * (1.0f + tanhf(inner));
            g_z[(chunk * CHUNK + j) * H + h] = z;
        }
    }
}

// ---------------- fused dual GEMM + gate + residual ----------------
// out_h = h + (z@W1^T + b1) * sigmoid(z@W2^T + b2)
// 64x64 tile, TK=16, 256 threads, 4x4 microtile per thread, both B matrices
__global__ void gemm_kernel(const float* __restrict__ w1, const float* __restrict__ b1,
                            const float* __restrict__ w2, const float* __restrict__ b2) {
    __shared__ float As [16][64];
    __shared__ float B1s[16][64];
    __shared__ float B2s[16][64];
    int l0 = blockIdx.x * 64, o0 = blockIdx.y * 64;
    int tid = threadIdx.x;
    int ty = tid >> 4, tx = tid & 15;                  // 16x16 thread grid
    int lm = tid >> 2, lq = (tid & 3) * 4;             // loader: row, col-quad
    float acc1[16], acc2[16];
    #pragma unroll
    for (int i = 0; i < 16; i++) { acc1[i] = 0.0f; acc2[i] = 0.0f; }

    for (int k0 = 0; k0 < H; k0 += 16) {
        float4 av = *(const float4*)&g_z[(l0 + lm) * H + k0 + lq];
        float4 w1v = *(const float4*)&w1[(o0 + lm) * H + k0 + lq];
        float4 w2v = *(const float4*)&w2[(o0 + lm) * H + k0 + lq];
        As [lq + 0][lm] = av.x;  As [lq + 1][lm] = av.y;  As [lq + 2][lm] = av.z;  As [lq + 3][lm] = av.w;
        B1s[lq + 0][lm] = w1v.x; B1s[lq + 1][lm] = w1v.y; B1s[lq + 2][lm] = w1v.z; B1s[lq + 3][lm] = w1v.w;
        B2s[lq + 0][lm] = w2v.x; B2s[lq + 1][lm] = w2v.y; B2s[lq + 2][lm] = w2v.z; B2s[lq + 3][lm] = w2v.w;
        __syncthreads();
        #pragma unroll
        for (int kk = 0; kk < 16; kk++) {
            float a[4], p[4], q[4];
            #pragma unroll
            for (int i = 0; i < 4; i++) a[i] = As[kk][ty * 4 + i];
            #pragma unroll
            for (int j = 0; j < 4; j++) { p[j] = B1s[kk][tx * 4 + j]; q[j] = B2s[kk][tx * 4 + j]; }
            #pragma unroll
            for (int i = 0; i < 4; i++)
                #pragma unroll
                for (int j = 0; j < 4; j++) {
                    acc1[i * 4 + j] = fmaf(a[i], p[j], acc1[i * 4 + j]);
                    acc2[i * 4 + j] = fmaf(a[i], q[j], acc2[i * 4 + j]);
                }
        }
        __syncthreads();
    }
    #pragma unroll
    for (int i = 0; i < 4; i++) {
        int l = l0 + ty * 4 + i;
        #pragma unroll
        for (int j = 0; j < 4; j++) {
            int o = o0 + tx * 4 + j;
            float p1 = acc1[i * 4 + j] + b1[o];
            float p2 = acc2[i * 4 + j] + b2[o];
            float sig = 1.0f / (1.0f + expf(-p2));
            g_h[l * H + o] += p1 * sig;
        }
    }
}

// ---------------- decoder: one warp per (l,o) ----------------
__global__ void dec_kernel(const float* __restrict__ w, const float* __restrict__ b,
                           float* __restrict__ out) {
    int wid = (blockIdx.x * blockDim.x + threadIdx.x) >> 5;
    int lane = threadIdx.x & 31;
    if (wid >= L * 3) return;
    int l = wid / 3, o = wid % 3;
    float s = 0.0f;
    #pragma unroll
    for (int q = 0; q < 16; q++)
        s = fmaf(g_h[l * H + lane + q * 32], w[o * H + lane + q * 32], s);
    for (int off = 16; off; off >>= 1) s += __shfl_xor_sync(0xffffffffu, s, off);
    if (lane == 0) out[l * 3 + o] = s + b[o];
}

// ---------------- launch ----------------
extern "C" void kernel_launch(void* const* d_in, const int* in_sizes, int n_in,
                              void* d_out, int out_size) {
    const float* x        = (const float*)d_in[0];
    const float* enc_w    = (const float*)d_in[1];
    const float* enc_b    = (const float*)d_in[2];
    const float* dec_w    = (const float*)d_in[3];
    const float* dec_b    = (const float*)d_in[4];
    const float* norm_w   = (const float*)d_in[5];
    const float* norm_b   = (const float*)d_in[6];
    const float* lam_re   = (const float*)d_in[7];
    const float* lam_im   = (const float*)d_in[8];
    const float* b_re     = (const float*)d_in[9];
    const float* b_im     = (const float*)d_in[10];
    const float* c_re     = (const float*)d_in[11];
    const float* c_im     = (const float*)d_in[12];
    const float* dvec     = (const float*)d_in[13];
    const float* log_step = (const float*)d_in[14];
    const float* out_w    = (const float*)d_in[15];
    const float* out_b    = (const float*)d_in[16];
    const float* out2_w   = (const float*)d_in[17];
    const float* out2_b   = (const float*)d_in[18];
    float* out = (float*)d_out;

    enc_kernel<<<(L * H) / 256, 256>>>(x, enc_w, enc_b);
    for (int i = 0; i < NLAY; i++) {
        size_t oHN = (size_t)i * H * NS, oH = (size_t)i * H, oHH = (size_t)i * H * H;
        pre_kernel<<<(H * NS) / 256, 256>>>(lam_re + oHN, lam_im + oHN,
                                            b_re + oHN, b_im + oHN, log_step + oH);
        ln_kernel<<<L, 128>>>(norm_w + oH, norm_b + oH);
        scan1_kernel<<<dim3(NCH, H / 32), 128>>>();
        comb_kernel<<<(H * NS) / 256, 256>>>();
        scan3_kernel<<<dim3(NCH, H / 32), 128>>>(c_re + oHN, c_im + oHN, dvec + oH);
        gemm_kernel<<<dim3(L / 64, H / 64), 256>>>(out_w + oHH, out_b + oH,
                                                   out2_w + oHH, out2_b + oH);
    }
    dec_kernel<<<(L * 3 * 32) / 256, 256>>>(dec_w, dec_b, out);
}

// round 6
// speedup vs baseline: 1.3379x; 1.3379x over previous
#include <cuda_runtime.h>
#include <cuda_bf16.h>
#include <math.h>
#include <stdint.h>

#define L 2048
#define H 512
#define NS 32
#define NLAY 4
#define CHUNK 32
#define NCH (L / CHUNK)   // 64

// ---------------- persistent scratch (no cudaMalloc allowed) ----------------
__device__ float  g_h[L * H];          // residual stream
__device__ float  g_u[L * H];          // layernorm output (scan input)
__device__ __nv_bfloat16 g_zh[L * H];  // gelu(scan out) hi
__device__ __nv_bfloat16 g_zl[L * H];  // gelu(scan out) lo
__device__ __nv_bfloat16 g_w1h[NLAY * H * H], g_w1l[NLAY * H * H];
__device__ __nv_bfloat16 g_w2h[NLAY * H * H], g_w2l[NLAY * H * H];
__device__ float2 g_A[H * NS];         // Abar
__device__ float2 g_B[H * NS];         // Bbar
__device__ float2 g_Ap[H * NS];        // Abar^CHUNK
__device__ float2 g_sfin[NCH * H * NS];// per-chunk local final states
__device__ float2 g_sin [NCH * H * NS];// per-chunk initial states

// ---------------- encoder: h = x @ enc_w.T + enc_b ----------------
__global__ void enc_kernel(const float* __restrict__ x,
                           const float* __restrict__ w,
                           const float* __restrict__ b) {
    int idx = blockIdx.x * blockDim.x + threadIdx.x;   // L*H
    int l = idx >> 9, h = idx & 511;
    float4 xv = ((const float4*)x)[l];
    float4 wv = ((const float4*)w)[h];
    g_h[idx] = fmaf(xv.x, wv.x, fmaf(xv.y, wv.y, fmaf(xv.z, wv.z, fmaf(xv.w, wv.w, b[h]))));
}

// ---------------- weight conversion to bf16 hi/lo (once per launch) --------
__global__ void convw_kernel(const float* __restrict__ w1, const float* __restrict__ w2) {
    int i = blockIdx.x * blockDim.x + threadIdx.x;     // NLAY*H*H
    float a = w1[i];
    __nv_bfloat16 ah = __float2bfloat16(a);
    g_w1h[i] = ah; g_w1l[i] = __float2bfloat16(a - __bfloat162float(ah));
    float b = w2[i];
    __nv_bfloat16 bh = __float2bfloat16(b);
    g_w2h[i] = bh; g_w2l[i] = __float2bfloat16(b - __bfloat162float(bh));
}

// ---------------- layernorm: one block per row ----------------
__global__ void ln_kernel(const float* __restrict__ nw, const float* __restrict__ nb) {
    int l = blockIdx.x, t = threadIdx.x;               // 128 threads, float4 each
    float4 v = ((const float4*)(g_h + l * H))[t];
    float s = v.x + v.y + v.z + v.w;
    float q = v.x * v.x + v.y * v.y + v.z * v.z + v.w * v.w;
    for (int o = 16; o; o >>= 1) {
        s += __shfl_xor_sync(0xffffffffu, s, o);
        q += __shfl_xor_sync(0xffffffffu, q, o);
    }
    __shared__ float ss[4], sq[4];
    if ((t & 31) == 0) { ss[t >> 5] = s; sq[t >> 5] = q; }
    __syncthreads();
    s = ss[0] + ss[1] + ss[2] + ss[3];
    q = sq[0] + sq[1] + sq[2] + sq[3];
    float m = s * (1.0f / H);
    float var = q * (1.0f / H) - m * m;
    float r = rsqrtf(var + 1e-5f);
    float4 wv = ((const float4*)nw)[t], bv = ((const float4*)nb)[t];
    float4 o;
    o.x = fmaf((v.x - m) * r, wv.x, bv.x);
    o.y = fmaf((v.y - m) * r, wv.y, bv.y);
    o.z = fmaf((v.z - m) * r, wv.z, bv.z);
    o.w = fmaf((v.w - m) * r, wv.w, bv.w);
    ((float4*)(g_u + l * H))[t] = o;
}

// ---------------- per-layer discretization + A^CHUNK ----------------
__global__ void pre_kernel(const float* __restrict__ lre, const float* __restrict__ lim,
                           const float* __restrict__ bre, const float* __restrict__ bim,
                           const float* __restrict__ lstep) {
    int i = blockIdx.x * blockDim.x + threadIdx.x;     // H*NS
    int h = i >> 5;
    float st = expf(lstep[h]);
    float zr = 0.5f * st * lre[i], zi = 0.5f * st * lim[i];
    float dr = 1.0f - zr, di = -zi;                    // 1 - z
    float inv = 1.0f / (dr * dr + di * di);
    float blr = dr * inv, bli = -di * inv;             // BL = 1/(1-z)
    float nr = 1.0f + zr, ni = zi;                     // 1 + z
    float ar = blr * nr - bli * ni;
    float ai = blr * ni + bli * nr;
    float br_ = st * (blr * bre[i] - bli * bim[i]);
    float bi_ = st * (blr * bim[i] + bli * bre[i]);
    g_A[i] = make_float2(ar, ai);
    g_B[i] = make_float2(br_, bi_);
    float pr = ar, pi = ai;                            // A^32 via 5 squarings
    #pragma unroll
    for (int k = 0; k < 5; k++) { float tr = pr * pr - pi * pi; pi = 2.0f * pr * pi; pr = tr; }
    g_Ap[i] = make_float2(pr, pi);
}

// ---------------- scan pass 1: per-chunk local scan, zero init, states only --
__global__ void scan1_kernel() {
    int chunk = blockIdx.x, hb = blockIdx.y * 32;
    int t = threadIdx.x, chl = t >> 2, part = t & 3;
    int h = hb + chl, n0 = part * 8;
    __shared__ float us[CHUNK * 32];
    for (int i = t; i < CHUNK * 32; i += 128)
        us[i] = g_u[(chunk * CHUNK + (i >> 5)) * H + hb + (i & 31)];
    __syncthreads();
    float ar[8], ai[8], br[8], bi[8], sr[8], si[8];
    #pragma unroll
    for (int k = 0; k < 8; k++) {
        float2 a = g_A[h * NS + n0 + k]; ar[k] = a.x; ai[k] = a.y;
        float2 b = g_B[h * NS + n0 + k]; br[k] = b.x; bi[k] = b.y;
        sr[k] = 0.0f; si[k] = 0.0f;
    }
    #pragma unroll 4
    for (int j = 0; j < CHUNK; j++) {
        float u = us[j * 32 + chl];
        #pragma unroll
        for (int k = 0; k < 8; k++) {
            float nr = fmaf(ar[k], sr[k], fmaf(-ai[k], si[k], br[k] * u));
            float ni = fmaf(ar[k], si[k], fmaf( ai[k], sr[k], bi[k] * u));
            sr[k] = nr; si[k] = ni;
        }
    }
    #pragma unroll
    for (int k = 0; k < 8; k++)
        g_sfin[(chunk * H + h) * NS + n0 + k] = make_float2(sr[k], si[k]);
}

// ---------------- combine: propagate chunk-initial states ----------------
__global__ void comb_kernel() {
    int i = blockIdx.x * blockDim.x + threadIdx.x;     // H*NS
    float2 ap = g_Ap[i];
    float sr = 0.0f, si = 0.0f;
    #pragma unroll
    for (int c = 0; c < NCH; c++) {
        g_sin[c * H * NS + i] = make_float2(sr, si);
        float2 f = g_sfin[c * H * NS + i];
        float nr = ap.x * sr - ap.y * si + f.x;
        si      = ap.x * si + ap.y * sr + f.y;
        sr = nr;
    }
}

// ---------------- scan pass 3: full scan with init -> y -> gelu -> bf16 split
__global__ void scan3_kernel(const float* __restrict__ cre, const float* __restrict__ cim,
                             const float* __restrict__ dvec) {
    int chunk = blockIdx.x, hb = blockIdx.y * 32;
    int t = threadIdx.x, chl = t >> 2, part = t & 3;
    int h = hb + chl, n0 = part * 8;
    __shared__ float us[CHUNK * 32];
    for (int i = t; i < CHUNK * 32; i += 128)
        us[i] = g_u[(chunk * CHUNK + (i >> 5)) * H + hb + (i & 31)];
    __syncthreads();
    float ar[8], ai[8], br[8], bi[8], cr[8], ci[8], sr[8], si[8];
    #pragma unroll
    for (int k = 0; k < 8; k++) {
        int idx = h * NS + n0 + k;
        float2 a = g_A[idx]; ar[k] = a.x; ai[k] = a.y;
        float2 b = g_B[idx]; br[k] = b.x; bi[k] = b.y;
        cr[k] = cre[idx];    ci[k] = cim[idx];
        float2 s0 = g_sin[chunk * H * NS + idx]; sr[k] = s0.x; si[k] = s0.y;
    }
    float dh = dvec[h];
    for (int j = 0; j < CHUNK; j++) {
        float u = us[j * 32 + chl];
        float acc = 0.0f;
        #pragma unroll
        for (int k = 0; k < 8; k++) {
            float nr = fmaf(ar[k], sr[k], fmaf(-ai[k], si[k], br[k] * u));
            float ni = fmaf(ar[k], si[k], fmaf( ai[k], sr[k], bi[k] * u));
            sr[k] = nr; si[k] = ni;
            acc = fmaf(cr[k], sr[k], acc);
            acc = fmaf(-ci[k], si[k], acc);
        }
        acc += __shfl_xor_sync(0xffffffffu, acc, 1);
        acc += __shfl_xor_sync(0xffffffffu, acc, 2);
        if (part == 0) {
            float y = fmaf(2.0f, acc, dh * u);
            float inner = 0.7978845608028654f * fmaf(0.044715f * y, y * y, y);
            float z = 0.5f * y * (1.0f + tanhf(inner));
            __nv_bfloat16 zh = __float2bfloat16(z);
            int gi = (chunk * CHUNK + j) * H + h;
            g_zh[gi] = zh;
            g_zl[gi] = __float2bfloat16(z - __bfloat162float(zh));
        }
    }
}

// ================= warp-level HMMA dual GEMM (bf16 hi/lo split) =============
// out_h += (z@W1^T + b1) * sigmoid(z@W2^T + b2)
// CTA tile M=128 x N=64; 8 warps (4m x 2n), each warp 32x32 per GEMM.
// K=512 in 8 slabs of 64; mma.m16n8k16 row.col bf16; 3-term split per GEMM.

#define KS   64
#define PADR 72                      // padded row stride (bf16 elems)
#define OFF_AH  0
#define OFF_AL  (128 * PADR)
#define OFF_B1H (2 * 128 * PADR)
#define OFF_B1L (OFF_B1H + 64 * PADR)
#define OFF_B2H (OFF_B1H + 2 * 64 * PADR)
#define OFF_B2L (OFF_B1H + 3 * 64 * PADR)
#define GEMM_SMEM_ELEMS (OFF_B1H + 4 * 64 * PADR)
#define GEMM_SMEM_BYTES (GEMM_SMEM_ELEMS * 2)

__device__ __forceinline__ uint32_t smem_u32(const void* p) {
    uint32_t a;
    asm("{ .reg .u64 t; cvta.to.shared.u64 t, %1; cvt.u32.u64 %0, t; }" : "=r"(a) : "l"(p));
    return a;
}
__device__ __forceinline__ void ldsm4(uint32_t& r0, uint32_t& r1, uint32_t& r2, uint32_t& r3,
                                      uint32_t addr) {
    asm volatile("ldmatrix.sync.aligned.m8n8.x4.shared.b16 {%0,%1,%2,%3}, [%4];"
                 : "=r"(r0), "=r"(r1), "=r"(r2), "=r"(r3) : "r"(addr));
}
__device__ __forceinline__ void mma16816(float* d, const uint32_t* a, const uint32_t* b) {
    asm volatile(
        "mma.sync.aligned.m16n8k16.row.col.f32.bf16.bf16.f32 "
        "{%0,%1,%2,%3}, {%4,%5,%6,%7}, {%8,%9}, {%0,%1,%2,%3};"
        : "+f"(d[0]), "+f"(d[1]), "+f"(d[2]), "+f"(d[3])
        : "r"(a[0]), "r"(a[1]), "r"(a[2]), "r"(a[3]), "r"(b[0]), "r"(b[1]));
}

__global__ void __launch_bounds__(256)
gemm_hmma_kernel(int layer, const float* __restrict__ b1v, const float* __restrict__ b2v) {
    extern __shared__ __nv_bfloat16 sm[];
    int t = threadIdx.x, wid = t >> 5, lane = t & 31;
    int l0 = blockIdx.x * 128, o0 = blockIdx.y * 64;
    int warp_m = (wid & 3) * 32, warp_n = (wid >> 2) * 32;
    const __nv_bfloat16* w1h = g_w1h + (size_t)layer * H * H;
    const __nv_bfloat16* w1l = g_w1l + (size_t)layer * H * H;
    const __nv_bfloat16* w2h = g_w2h + (size_t)layer * H * H;
    const __nv_bfloat16* w2l = g_w2l + (size_t)layer * H * H;

    // ldmatrix lane addressing (bytes): A fragment (m16k16)
    int g8 = lane >> 3, rin = lane & 7;
    uint32_t sbase = smem_u32(sm);
    // A: r0 rows0-7 k0; r1 rows8-15 k0; r2 rows0-7 k8; r3 rows8-15 k8
    uint32_t a_lane_off = (uint32_t)(((g8 & 1) * 8 + rin) * (PADR * 2) + (g8 >> 1) * 16);
    // B: r0 n0-7 k0; r1 n0-7 k8; r2 n8-15 k0; r3 n8-15 k8
    uint32_t b_lane_off = (uint32_t)((((g8 >> 1) & 1) * 8 + rin) * (PADR * 2) + (g8 & 1) * 16);

    float acc1[2][4][4], acc2[2][4][4];
    #pragma unroll
    for (int i = 0; i < 2; i++)
        #pragma unroll
        for (int j = 0; j < 4; j++)
            #pragma unroll
            for (int k = 0; k < 4; k++) { acc1[i][j][k] = 0.0f; acc2[i][j][k] = 0.0f; }

    for (int s = 0; s < 8; s++) {
        int k0 = s * KS;
        // ---- load slab into smem (256 threads) ----
        {
            int row = t >> 1, half = t & 1;            // A: 128 rows x 2 halves
            const uint4* srcH = (const uint4*)(g_zh + (size_t)(l0 + row) * H + k0 + half * 32);
            const uint4* srcL = (const uint4*)(g_zl + (size_t)(l0 + row) * H + k0 + half * 32);
            uint4* dstH = (uint4*)(sm + OFF_AH + row * PADR + half * 32);
            uint4* dstL = (uint4*)(sm + OFF_AL + row * PADR + half * 32);
            #pragma unroll
            for (int j = 0; j < 4; j++) { dstH[j] = srcH[j]; dstL[j] = srcL[j]; }
            // B: 4 matrices x 64 rows x 2 halves = 512 units, 2 per thread
            #pragma unroll
            for (int uu = 0; uu < 2; uu++) {
                int u = t + uu * 256;
                int mi = u >> 7, br = (u >> 1) & 63, bh = u & 1;
                const __nv_bfloat16* wsrc = (mi == 0) ? w1h : (mi == 1) ? w1l : (mi == 2) ? w2h : w2l;
                int doff = OFF_B1H + mi * 64 * PADR;
                const uint4* srcB = (const uint4*)(wsrc + (size_t)(o0 + br) * H + k0 + bh * 32);
                uint4* dstB = (uint4*)(sm + doff + br * PADR + bh * 32);
                #pragma unroll
                for (int j = 0; j < 4; j++) dstB[j] = srcB[j];
            }
        }
        __syncthreads();
        // ---- compute: 4 k16 steps ----
        #pragma unroll
        for (int kk = 0; kk < 4; kk++) {
            uint32_t koff = kk * 32;                   // bytes within row
            uint32_t ah[2][4], al[2][4];
            #pragma unroll
            for (int mt = 0; mt < 2; mt++) {
                uint32_t rowb = (uint32_t)((warp_m + mt * 16) * (PADR * 2));
                ldsm4(ah[mt][0], ah[mt][1], ah[mt][2], ah[mt][3],
                      sbase + OFF_AH * 2 + rowb + a_lane_off + koff);
                ldsm4(al[mt][0], al[mt][1], al[mt][2], al[mt][3],
                      sbase + OFF_AL * 2 + rowb + a_lane_off + koff);
            }
            uint32_t bf[4][2][4];                      // [matrix][n-pair][reg]
            #pragma unroll
            for (int mi = 0; mi < 4; mi++) {
                uint32_t mbase = sbase + (OFF_B1H + mi * 64 * PADR) * 2;
                #pragma unroll
                for (int np = 0; np < 2; np++) {
                    uint32_t rowb = (uint32_t)((warp_n + np * 16) * (PADR * 2));
                    ldsm4(bf[mi][np][0], bf[mi][np][1], bf[mi][np][2], bf[mi][np][3],
                          mbase + rowb + b_lane_off + koff);
                }
            }
            #pragma unroll
            for (int mt = 0; mt < 2; mt++)
                #pragma unroll
                for (int nt = 0; nt < 4; nt++) {
                    const uint32_t* b1h = &bf[0][nt >> 1][(nt & 1) * 2];
                    const uint32_t* b1l = &bf[1][nt >> 1][(nt & 1) * 2];
                    const uint32_t* b2h = &bf[2][nt >> 1][(nt & 1) * 2];
                    const uint32_t* b2l = &bf[3][nt >> 1][(nt & 1) * 2];
                    mma16816(acc1[mt][nt], ah[mt], b1h);
                    mma16816(acc1[mt][nt], ah[mt], b1l);
                    mma16816(acc1[mt][nt], al[mt], b1h);
                    mma16816(acc2[mt][nt], ah[mt], b2h);
                    mma16816(acc2[mt][nt], ah[mt], b2l);
                    mma16816(acc2[mt][nt], al[mt], b2h);
                }
        }
        __syncthreads();
    }

    // ---- epilogue: gate + residual ----
    int qr = lane >> 2, qc = (lane & 3) * 2;
    #pragma unroll
    for (int mt = 0; mt < 2; mt++)
        #pragma unroll
        for (int nt = 0; nt < 4; nt++) {
            int c = o0 + warp_n + nt * 8 + qc;
            float bb1a = b1v[c], bb1b = b1v[c + 1];
            float bb2a = b2v[c], bb2b = b2v[c + 1];
            #pragma unroll
            for (int rr = 0; rr < 2; rr++) {
                int r = l0 + warp_m + mt * 16 + qr + rr * 8;
                float p1a = acc1[mt][nt][rr * 2 + 0] + bb1a;
                float p1b = acc1[mt][nt][rr * 2 + 1] + bb1b;
                float p2a = acc2[mt][nt][rr * 2 + 0] + bb2a;
                float p2b = acc2[mt][nt][rr * 2 + 1] + bb2b;
                float* hp = g_h + (size_t)r * H + c;
                hp[0] += p1a / (1.0f + expf(-p2a));
                hp[1] += p1b / (1.0f + expf(-p2b));
            }
        }
}

// ---------------- decoder: one warp per (l,o) ----------------
__global__ void dec_kernel(const float* __restrict__ w, const float* __restrict__ b,
                           float* __restrict__ out) {
    int wid = (blockIdx.x * blockDim.x + threadIdx.x) >> 5;
    int lane = threadIdx.x & 31;
    if (wid >= L * 3) return;
    int l = wid / 3, o = wid % 3;
    float s = 0.0f;
    #pragma unroll
    for (int q = 0; q < 16; q++)
        s = fmaf(g_h[l * H + lane + q * 32], w[o * H + lane + q * 32], s);
    for (int off = 16; off; off >>= 1) s += __shfl_xor_sync(0xffffffffu, s, off);
    if (lane == 0) out[l * 3 + o] = s + b[o];
}

// ---------------- launch ----------------
extern "C" void kernel_launch(void* const* d_in, const int* in_sizes, int n_in,
                              void* d_out, int out_size) {
    const float* x        = (const float*)d_in[0];
    const float* enc_w    = (const float*)d_in[1];
    const float* enc_b    = (const float*)d_in[2];
    const float* dec_w    = (const float*)d_in[3];
    const float* dec_b    = (const float*)d_in[4];
    const float* norm_w   = (const float*)d_in[5];
    const float* norm_b   = (const float*)d_in[6];
    const float* lam_re   = (const float*)d_in[7];
    const float* lam_im   = (const float*)d_in[8];
    const float* b_re     = (const float*)d_in[9];
    const float* b_im     = (const float*)d_in[10];
    const float* c_re     = (const float*)d_in[11];
    const float* c_im     = (const float*)d_in[12];
    const float* dvec     = (const float*)d_in[13];
    const float* log_step = (const float*)d_in[14];
    const float* out_w    = (const float*)d_in[15];
    const float* out_b    = (const float*)d_in[16];
    const float* out2_w   = (const float*)d_in[17];
    const float* out2_b   = (const float*)d_in[18];
    float* out = (float*)d_out;

    cudaFuncSetAttribute(gemm_hmma_kernel, cudaFuncAttributeMaxDynamicSharedMemorySize,
                         GEMM_SMEM_BYTES);

    enc_kernel<<<(L * H) / 256, 256>>>(x, enc_w, enc_b);
    convw_kernel<<<(NLAY * H * H) / 256, 256>>>(out_w, out2_w);
    for (int i = 0; i < NLAY; i++) {
        size_t oHN = (size_t)i * H * NS, oH = (size_t)i * H;
        pre_kernel<<<(H * NS) / 256, 256>>>(lam_re + oHN, lam_im + oHN,
                                            b_re + oHN, b_im + oHN, log_step + oH);
        ln_kernel<<<L, 128>>>(norm_w + oH, norm_b + oH);
        scan1_kernel<<<dim3(NCH, H / 32), 128>>>();
        comb_kernel<<<(H * NS) / 256, 256>>>();
        scan3_kernel<<<dim3(NCH, H / 32), 128>>>(c_re + oHN, c_im + oHN, dvec + oH);
        gemm_hmma_kernel<<<dim3(L / 128, H / 64), 256, GEMM_SMEM_BYTES>>>(
            i, out_b + oH, out2_b + oH);
    }
    dec_kernel<<<(L * 3 * 32) / 256, 256>>>(dec_w, dec_b, out);
}

// round 7
// speedup vs baseline: 1.4665x; 1.0961x over previous
#include <cuda_runtime.h>
#include <cuda_bf16.h>
#include <math.h>
#include <stdint.h>

#define L 2048
#define H 512
#define NS 32
#define NLAY 4
#define CHUNK 32
#define NCH (L / CHUNK)   // 64

// ---------------- persistent scratch (no cudaMalloc allowed) ----------------
__device__ float  g_h[L * H];          // residual stream
__device__ float  g_u[L * H];          // layernorm output (scan input)
__device__ __nv_bfloat16 g_zh[L * H];  // gelu(scan out) hi
__device__ __nv_bfloat16 g_zl[L * H];  // gelu(scan out) lo
__device__ __nv_bfloat16 g_w1h[NLAY * H * H], g_w1l[NLAY * H * H];
__device__ __nv_bfloat16 g_w2h[NLAY * H * H], g_w2l[NLAY * H * H];
__device__ float2 g_A[NLAY * H * NS];  // Abar
__device__ float2 g_B[NLAY * H * NS];  // Bbar
__device__ float2 g_Ap[NLAY * H * NS]; // Abar^CHUNK
__device__ float2 g_sfin[NCH * H * NS];// per-chunk local final states
__device__ float2 g_sin [NCH * H * NS];// per-chunk initial states

// ---------------- encoder: h = x @ enc_w.T + enc_b ----------------
__global__ void enc_kernel(const float* __restrict__ x,
                           const float* __restrict__ w,
                           const float* __restrict__ b) {
    int idx = blockIdx.x * blockDim.x + threadIdx.x;   // L*H
    int l = idx >> 9, h = idx & 511;
    float4 xv = ((const float4*)x)[l];
    float4 wv = ((const float4*)w)[h];
    g_h[idx] = fmaf(xv.x, wv.x, fmaf(xv.y, wv.y, fmaf(xv.z, wv.z, fmaf(xv.w, wv.w, b[h]))));
}

// ---------------- weight conversion to bf16 hi/lo (once per launch) --------
__global__ void convw_kernel(const float* __restrict__ w1, const float* __restrict__ w2) {
    int i = blockIdx.x * blockDim.x + threadIdx.x;     // NLAY*H*H
    float a = w1[i];
    __nv_bfloat16 ah = __float2bfloat16(a);
    g_w1h[i] = ah; g_w1l[i] = __float2bfloat16(a - __bfloat162float(ah));
    float b = w2[i];
    __nv_bfloat16 bh = __float2bfloat16(b);
    g_w2h[i] = bh; g_w2l[i] = __float2bfloat16(b - __bfloat162float(bh));
}

// ---------------- layernorm: one block per row ----------------
__global__ void ln_kernel(const float* __restrict__ nw, const float* __restrict__ nb) {
    int l = blockIdx.x, t = threadIdx.x;               // 128 threads, float4 each
    float4 v = ((const float4*)(g_h + l * H))[t];
    float s = v.x + v.y + v.z + v.w;
    float q = v.x * v.x + v.y * v.y + v.z * v.z + v.w * v.w;
    for (int o = 16; o; o >>= 1) {
        s += __shfl_xor_sync(0xffffffffu, s, o);
        q += __shfl_xor_sync(0xffffffffu, q, o);
    }
    __shared__ float ss[4], sq[4];
    if ((t & 31) == 0) { ss[t >> 5] = s; sq[t >> 5] = q; }
    __syncthreads();
    s = ss[0] + ss[1] + ss[2] + ss[3];
    q = sq[0] + sq[1] + sq[2] + sq[3];
    float m = s * (1.0f / H);
    float var = q * (1.0f / H) - m * m;
    float r = rsqrtf(var + 1e-5f);
    float4 wv = ((const float4*)nw)[t], bv = ((const float4*)nb)[t];
    float4 o;
    o.x = fmaf((v.x - m) * r, wv.x, bv.x);
    o.y = fmaf((v.y - m) * r, wv.y, bv.y);
    o.z = fmaf((v.z - m) * r, wv.z, bv.z);
    o.w = fmaf((v.w - m) * r, wv.w, bv.w);
    ((float4*)(g_u + l * H))[t] = o;
}

// ---------------- ALL layers discretization + A^CHUNK (one launch) ---------
__global__ void pre_kernel(const float* __restrict__ lre, const float* __restrict__ lim,
                           const float* __restrict__ bre, const float* __restrict__ bim,
                           const float* __restrict__ lstep) {
    int i = blockIdx.x * blockDim.x + threadIdx.x;     // NLAY*H*NS
    int layer = i >> 14;                               // H*NS = 16384
    int hloc = (i >> 5) & 511;
    float st = expf(lstep[layer * H + hloc]);
    float zr = 0.5f * st * lre[i], zi = 0.5f * st * lim[i];
    float dr = 1.0f - zr, di = -zi;                    // 1 - z
    float inv = 1.0f / (dr * dr + di * di);
    float blr = dr * inv, bli = -di * inv;             // BL = 1/(1-z)
    float nr = 1.0f + zr, ni = zi;                     // 1 + z
    float ar = blr * nr - bli * ni;
    float ai = blr * ni + bli * nr;
    float br_ = st * (blr * bre[i] - bli * bim[i]);
    float bi_ = st * (blr * bim[i] + bli * bre[i]);
    g_A[i] = make_float2(ar, ai);
    g_B[i] = make_float2(br_, bi_);
    float pr = ar, pi = ai;                            // A^32 via 5 squarings
    #pragma unroll
    for (int k = 0; k < 5; k++) { float tr = pr * pr - pi * pi; pi = 2.0f * pr * pi; pr = tr; }
    g_Ap[i] = make_float2(pr, pi);
}

// ---------------- scan pass 1: per-chunk local scan, zero init, states only --
__global__ void scan1_kernel(int layer) {
    int chunk = blockIdx.x, hb = blockIdx.y * 32;
    int t = threadIdx.x, chl = t >> 2, part = t & 3;
    int h = hb + chl, n0 = part * 8;
    int lb = layer * H * NS;
    __shared__ float us[CHUNK * 32];
    for (int i = t; i < CHUNK * 32; i += 128)
        us[i] = g_u[(chunk * CHUNK + (i >> 5)) * H + hb + (i & 31)];
    __syncthreads();
    float ar[8], ai[8], br[8], bi[8], sr[8], si[8];
    #pragma unroll
    for (int k = 0; k < 8; k++) {
        float2 a = g_A[lb + h * NS + n0 + k]; ar[k] = a.x; ai[k] = a.y;
        float2 b = g_B[lb + h * NS + n0 + k]; br[k] = b.x; bi[k] = b.y;
        sr[k] = 0.0f; si[k] = 0.0f;
    }
    #pragma unroll 4
    for (int j = 0; j < CHUNK; j++) {
        float u = us[j * 32 + chl];
        #pragma unroll
        for (int k = 0; k < 8; k++) {
            float nr = fmaf(ar[k], sr[k], fmaf(-ai[k], si[k], br[k] * u));
            float ni = fmaf(ar[k], si[k], fmaf( ai[k], sr[k], bi[k] * u));
            sr[k] = nr; si[k] = ni;
        }
    }
    #pragma unroll
    for (int k = 0; k < 8; k++)
        g_sfin[(chunk * H + h) * NS + n0 + k] = make_float2(sr[k], si[k]);
}

// ---------------- combine: propagate chunk-initial states ----------------
__global__ void comb_kernel(int layer) {
    int i = blockIdx.x * blockDim.x + threadIdx.x;     // H*NS
    float2 ap = g_Ap[layer * H * NS + i];
    float sr = 0.0f, si = 0.0f;
    #pragma unroll
    for (int c = 0; c < NCH; c++) {
        g_sin[c * H * NS + i] = make_float2(sr, si);
        float2 f = g_sfin[c * H * NS + i];
        float nr = ap.x * sr - ap.y * si + f.x;
        si      = ap.x * si + ap.y * sr + f.y;
        sr = nr;
    }
}

// ---------------- scan pass 3: full scan with init -> y -> gelu -> bf16 split
__global__ void scan3_kernel(int layer, const float* __restrict__ cre,
                             const float* __restrict__ cim, const float* __restrict__ dvec) {
    int chunk = blockIdx.x, hb = blockIdx.y * 32;
    int t = threadIdx.x, chl = t >> 2, part = t & 3;
    int h = hb + chl, n0 = part * 8;
    int lb = layer * H * NS;
    __shared__ float us[CHUNK * 32];
    for (int i = t; i < CHUNK * 32; i += 128)
        us[i] = g_u[(chunk * CHUNK + (i >> 5)) * H + hb + (i & 31)];
    __syncthreads();
    float ar[8], ai[8], br[8], bi[8], cr[8], ci[8], sr[8], si[8];
    #pragma unroll
    for (int k = 0; k < 8; k++) {
        int idx = h * NS + n0 + k;
        float2 a = g_A[lb + idx]; ar[k] = a.x; ai[k] = a.y;
        float2 b = g_B[lb + idx]; br[k] = b.x; bi[k] = b.y;
        cr[k] = cre[idx];    ci[k] = cim[idx];
        float2 s0 = g_sin[chunk * H * NS + idx]; sr[k] = s0.x; si[k] = s0.y;
    }
    float dh = dvec[h];
    for (int j = 0; j < CHUNK; j++) {
        float u = us[j * 32 + chl];
        float acc = 0.0f;
        #pragma unroll
        for (int k = 0; k < 8; k++) {
            float nr = fmaf(ar[k], sr[k], fmaf(-ai[k], si[k], br[k] * u));
            float ni = fmaf(ar[k], si[k], fmaf( ai[k], sr[k], bi[k] * u));
            sr[k] = nr; si[k] = ni;
            acc = fmaf(cr[k], sr[k], acc);
            acc = fmaf(-ci[k], si[k], acc);
        }
        acc += __shfl_xor_sync(0xffffffffu, acc, 1);
        acc += __shfl_xor_sync(0xffffffffu, acc, 2);
        if (part == 0) {
            float y = fmaf(2.0f, acc, dh * u);
            float inner = 0.7978845608028654f * fmaf(0.044715f * y, y * y, y);
            float z = 0.5f * y * (1.0f + tanhf(inner));
            __nv_bfloat16 zh = __float2bfloat16(z);
            int gi = (chunk * CHUNK + j) * H + h;
            g_zh[gi] = zh;
            g_zl[gi] = __float2bfloat16(z - __bfloat162float(zh));
        }
    }
}

// ================= HMMA dual GEMM, cp.async double-buffered =================
// out_h += (z@W1^T + b1) * sigmoid(z@W2^T + b2)
// CTA tile M=128 x N=64; 8 warps (4m x 2n); K=512 in 8 slabs of 64.
// 2-stage cp.async pipeline; mma.m16n8k16 bf16, 3-term hi/lo split per GEMM.

#define KS   64
#define PADR 72                      // padded row stride (bf16 elems)
#define OFF_AH  0
#define OFF_AL  (128 * PADR)
#define OFF_B1H (2 * 128 * PADR)
#define OFF_B1L (OFF_B1H + 64 * PADR)
#define OFF_B2H (OFF_B1H + 2 * 64 * PADR)
#define OFF_B2L (OFF_B1H + 3 * 64 * PADR)
#define STAGE_ELEMS (OFF_B1H + 4 * 64 * PADR)      // 36864 elems
#define STAGE_BYTES (STAGE_ELEMS * 2)              // 73728 B
#define GEMM_SMEM_BYTES (2 * STAGE_BYTES)          // 147456 B

__device__ __forceinline__ uint32_t smem_u32(const void* p) {
    uint32_t a;
    asm("{ .reg .u64 t; cvta.to.shared.u64 t, %1; cvt.u32.u64 %0, t; }" : "=r"(a) : "l"(p));
    return a;
}
__device__ __forceinline__ void cp16(uint32_t saddr, const void* g) {
    asm volatile("cp.async.cg.shared.global [%0], [%1], 16;" :: "r"(saddr), "l"(g));
}
__device__ __forceinline__ void cp_commit() { asm volatile("cp.async.commit_group;"); }
__device__ __forceinline__ void cp_wait1() { asm volatile("cp.async.wait_group 1;"); }
__device__ __forceinline__ void cp_wait0() { asm volatile("cp.async.wait_group 0;"); }
__device__ __forceinline__ void ldsm4(uint32_t& r0, uint32_t& r1, uint32_t& r2, uint32_t& r3,
                                      uint32_t addr) {
    asm volatile("ldmatrix.sync.aligned.m8n8.x4.shared.b16 {%0,%1,%2,%3}, [%4];"
                 : "=r"(r0), "=r"(r1), "=r"(r2), "=r"(r3) : "r"(addr));
}
__device__ __forceinline__ void mma16816(float* d, const uint32_t* a, const uint32_t* b) {
    asm volatile(
        "mma.sync.aligned.m16n8k16.row.col.f32.bf16.bf16.f32 "
        "{%0,%1,%2,%3}, {%4,%5,%6,%7}, {%8,%9}, {%0,%1,%2,%3};"
        : "+f"(d[0]), "+f"(d[1]), "+f"(d[2]), "+f"(d[3])
        : "r"(a[0]), "r"(a[1]), "r"(a[2]), "r"(a[3]), "r"(b[0]), "r"(b[1]));
}

__global__ void __launch_bounds__(256)
gemm_hmma_kernel(int layer, const float* __restrict__ b1v, const float* __restrict__ b2v) {
    extern __shared__ __nv_bfloat16 sm[];
    int t = threadIdx.x, wid = t >> 5, lane = t & 31;
    int l0 = blockIdx.x * 128, o0 = blockIdx.y * 64;
    int warp_m = (wid & 3) * 32, warp_n = (wid >> 2) * 32;
    const __nv_bfloat16* w1h = g_w1h + (size_t)layer * H * H;
    const __nv_bfloat16* w1l = g_w1l + (size_t)layer * H * H;
    const __nv_bfloat16* w2h = g_w2h + (size_t)layer * H * H;
    const __nv_bfloat16* w2l = g_w2l + (size_t)layer * H * H;
    uint32_t sbase = smem_u32(sm);

    // cp.async load of one slab into stage buffer (8 A-chunks + 8 B-chunks per thread)
    auto load_slab = [&](int s, int stage) {
        uint32_t sb = sbase + (uint32_t)stage * STAGE_BYTES;
        int k0 = s * KS;
        #pragma unroll
        for (int j = 0; j < 8; j++) {
            int c = t + j * 256;                       // A: 2048 chunks
            int mat = c >> 10, row = (c >> 3) & 127, ch = c & 7;
            const __nv_bfloat16* src = (mat ? g_zl : g_zh);
            cp16(sb + (uint32_t)((mat ? OFF_AL : OFF_AH) + row * PADR + ch * 8) * 2,
                 src + (size_t)(l0 + row) * H + k0 + ch * 8);
        }
        #pragma unroll
        for (int j = 0; j < 8; j++) {
            int c = t + j * 256;                       // B: 2048 chunks
            int mat = c >> 9, row = (c >> 3) & 63, ch = c & 7;
            const __nv_bfloat16* src = (mat == 0) ? w1h : (mat == 1) ? w1l
                                     : (mat == 2) ? w2h : w2l;
            cp16(sb + (uint32_t)(OFF_B1H + mat * 64 * PADR + row * PADR + ch * 8) * 2,
                 src + (size_t)(o0 + row) * H + k0 + ch * 8);
        }
        cp_commit();
    };

    // ldmatrix lane addressing (bytes)
    int g8 = lane >> 3, rin = lane & 7;
    uint32_t a_lane_off = (uint32_t)(((g8 & 1) * 8 + rin) * (PADR * 2) + (g8 >> 1) * 16);
    uint32_t b_lane_off = (uint32_t)((((g8 >> 1) & 1) * 8 + rin) * (PADR * 2) + (g8 & 1) * 16);

    float acc1[2][4][4], acc2[2][4][4];
    #pragma unroll
    for (int i = 0; i < 2; i++)
        #pragma unroll
        for (int j = 0; j < 4; j++)
            #pragma unroll
            for (int k = 0; k < 4; k++) { acc1[i][j][k] = 0.0f; acc2[i][j][k] = 0.0f; }

    load_slab(0, 0);
    load_slab(1, 1);

    for (int s = 0; s < 8; s++) {
        if (s < 7) cp_wait1(); else cp_wait0();
        __syncthreads();
        uint32_t stb = sbase + (uint32_t)(s & 1) * STAGE_BYTES;
        #pragma unroll
        for (int kk = 0; kk < 4; kk++) {
            uint32_t koff = kk * 32;
            uint32_t ah[2][4], al[2][4];
            #pragma unroll
            for (int mt = 0; mt < 2; mt++) {
                uint32_t rowb = (uint32_t)((warp_m + mt * 16) * (PADR * 2));
                ldsm4(ah[mt][0], ah[mt][1], ah[mt][2], ah[mt][3],
                      stb + OFF_AH * 2 + rowb + a_lane_off + koff);
                ldsm4(al[mt][0], al[mt][1], al[mt][2], al[mt][3],
                      stb + OFF_AL * 2 + rowb + a_lane_off + koff);
            }
            uint32_t bf[4][2][4];
            #pragma unroll
            for (int mi = 0; mi < 4; mi++) {
                uint32_t mbase = stb + (OFF_B1H + mi * 64 * PADR) * 2;
                #pragma unroll
                for (int np = 0; np < 2; np++) {
                    uint32_t rowb = (uint32_t)((warp_n + np * 16) * (PADR * 2));
                    ldsm4(bf[mi][np][0], bf[mi][np][1], bf[mi][np][2], bf[mi][np][3],
                          mbase + rowb + b_lane_off + koff);
                }
            }
            #pragma unroll
            for (int mt = 0; mt < 2; mt++)
                #pragma unroll
                for (int nt = 0; nt < 4; nt++) {
                    const uint32_t* b1h = &bf[0][nt >> 1][(nt & 1) * 2];
                    const uint32_t* b1l = &bf[1][nt >> 1][(nt & 1) * 2];
                    const uint32_t* b2h = &bf[2][nt >> 1][(nt & 1) * 2];
                    const uint32_t* b2l = &bf[3][nt >> 1][(nt & 1) * 2];
                    mma16816(acc1[mt][nt], ah[mt], b1h);
                    mma16816(acc1[mt][nt], ah[mt], b1l);
                    mma16816(acc1[mt][nt], al[mt], b1h);
                    mma16816(acc2[mt][nt], ah[mt], b2h);
                    mma16816(acc2[mt][nt], ah[mt], b2l);
                    mma16816(acc2[mt][nt], al[mt], b2h);
                }
        }
        __syncthreads();
        if (s + 2 < 8) load_slab(s + 2, s & 1);
    }

    // ---- epilogue: gate + residual ----
    int qr = lane >> 2, qc = (lane & 3) * 2;
    #pragma unroll
    for (int mt = 0; mt < 2; mt++)
        #pragma unroll
        for (int nt = 0; nt < 4; nt++) {
            int c = o0 + warp_n + nt * 8 + qc;
            float bb1a = b1v[c], bb1b = b1v[c + 1];
            float bb2a = b2v[c], bb2b = b2v[c + 1];
            #pragma unroll
            for (int rr = 0; rr < 2; rr++) {
                int r = l0 + warp_m + mt * 16 + qr + rr * 8;
                float p1a = acc1[mt][nt][rr * 2 + 0] + bb1a;
                float p1b = acc1[mt][nt][rr * 2 + 1] + bb1b;
                float p2a = acc2[mt][nt][rr * 2 + 0] + bb2a;
                float p2b = acc2[mt][nt][rr * 2 + 1] + bb2b;
                float* hp = g_h + (size_t)r * H + c;
                hp[0] += p1a / (1.0f + expf(-p2a));
                hp[1] += p1b / (1.0f + expf(-p2b));
            }
        }
}

// ---------------- decoder: one warp per (l,o) ----------------
__global__ void dec_kernel(const float* __restrict__ w, const float* __restrict__ b,
                           float* __restrict__ out) {
    int wid = (blockIdx.x * blockDim.x + threadIdx.x) >> 5;
    int lane = threadIdx.x & 31;
    if (wid >= L * 3) return;
    int l = wid / 3, o = wid % 3;
    float s = 0.0f;
    #pragma unroll
    for (int q = 0; q < 16; q++)
        s = fmaf(g_h[l * H + lane + q * 32], w[o * H + lane + q * 32], s);
    for (int off = 16; off; off >>= 1) s += __shfl_xor_sync(0xffffffffu, s, off);
    if (lane == 0) out[l * 3 + o] = s + b[o];
}

// ---------------- launch ----------------
extern "C" void kernel_launch(void* const* d_in, const int* in_sizes, int n_in,
                              void* d_out, int out_size) {
    const float* x        = (const float*)d_in[0];
    const float* enc_w    = (const float*)d_in[1];
    const float* enc_b    = (const float*)d_in[2];
    const float* dec_w    = (const float*)d_in[3];
    const float* dec_b    = (const float*)d_in[4];
    const float* norm_w   = (const float*)d_in[5];
    const float* norm_b   = (const float*)d_in[6];
    const float* lam_re   = (const float*)d_in[7];
    const float* lam_im   = (const float*)d_in[8];
    const float* b_re     = (const float*)d_in[9];
    const float* b_im     = (const float*)d_in[10];
    const float* c_re     = (const float*)d_in[11];
    const float* c_im     = (const float*)d_in[12];
    const float* dvec     = (const float*)d_in[13];
    const float* log_step = (const float*)d_in[14];
    const float* out_w    = (const float*)d_in[15];
    const float* out_b    = (const float*)d_in[16];
    const float* out2_w   = (const float*)d_in[17];
    const float* out2_b   = (const float*)d_in[18];
    float* out = (float*)d_out;

    cudaFuncSetAttribute(gemm_hmma_kernel, cudaFuncAttributeMaxDynamicSharedMemorySize,
                         GEMM_SMEM_BYTES);

    enc_kernel<<<(L * H) / 256, 256>>>(x, enc_w, enc_b);
    convw_kernel<<<(NLAY * H * H) / 256, 256>>>(out_w, out2_w);
    pre_kernel<<<(NLAY * H * NS) / 256, 256>>>(lam_re, lam_im, b_re, b_im, log_step);
    for (int i = 0; i < NLAY; i++) {
        size_t oHN = (size_t)i * H * NS, oH = (size_t)i * H;
        ln_kernel<<<L, 128>>>(norm_w + oH, norm_b + oH);
        scan1_kernel<<<dim3(NCH, H / 32), 128>>>(i);
        comb_kernel<<<(H * NS) / 256, 256>>>(i);
        scan3_kernel<<<dim3(NCH, H / 32), 128>>>(i, c_re + oHN, c_im + oHN, dvec + oH);
        gemm_hmma_kernel<<<dim3(L / 128, H / 64), 256, GEMM_SMEM_BYTES>>>(
            i, out_b + oH, out2_b + oH);
    }
    dec_kernel<<<(L * 3 * 32) / 256, 256>>>(dec_w, dec_b, out);
}